// round 2
// baseline (speedup 1.0000x reference)
#include <cuda_runtime.h>
#include <cuda_bf16.h>

// FFT long convolution: y[b, 0:L] = (1/(2L)) * linear_conv(x[b], h[b])
// B=4096 rows, L=8192, N=2L=16384-point FFTs, one CTA per row, fully in SMEM.
//
// Scheme (no bit-reversal): radix-4 DIF forward (natural -> base-4 digit-reversed),
// pointwise product in digit-reversed domain, radix-4 DIT inverse (-> natural).
// Scale 1/N^2 applied at pointwise (ifft 1/N + reference's 1/(2L)).

#define FFT_N      16384
#define SEQ_L      8192
#define NTHREADS   512
#define BF_PER_THR (FFT_N / 4 / NTHREADS)   // 8 butterflies/thread/stage

// Skewed physical index: strictly increasing => injective; spreads every
// power-of-4 stride across distinct 8-byte bank pairs (conflict-free LDS.64).
__device__ __forceinline__ int skew(int i) {
    return i + (i >> 4) + (i >> 8) + (i >> 12);
}

#define DATA_SKEW_SIZE 17473   // skew(16383)+1
#define TW_SKEW_SIZE   8735    // skew(8191)+1
#define SMEM_BYTES     ((DATA_SKEW_SIZE + TW_SKEW_SIZE) * (int)sizeof(float2))

__device__ __forceinline__ float2 cadd(float2 a, float2 b) { return make_float2(a.x + b.x, a.y + b.y); }
__device__ __forceinline__ float2 csub(float2 a, float2 b) { return make_float2(a.x - b.x, a.y - b.y); }
__device__ __forceinline__ float2 cmul(float2 a, float2 b) {
    return make_float2(fmaf(a.x, b.x, -(a.y * b.y)), fmaf(a.x, b.y, a.y * b.x));
}
// a * conj(b)
__device__ __forceinline__ float2 cmulc(float2 a, float2 b) {
    return make_float2(fmaf(a.x, b.x, a.y * b.y), fmaf(a.y, b.x, -(a.x * b.y)));
}

// Forward radix-4 DIF: natural input -> base-4 digit-reversed output, in place.
__device__ __forceinline__ void fft_fwd(float2* data, const float2* tw, int tid)
{
    for (int lm = 14; lm >= 2; lm -= 2) {
        const int qsh = lm - 2;
        const int q   = 1 << qsh;
        const int tsh = 14 - lm;
        #pragma unroll 4
        for (int r = 0; r < BF_PER_THR; r++) {
            int t    = tid + NTHREADS * r;         // butterfly id in [0, N/4)
            int j    = t & (q - 1);
            int blk  = t >> qsh;
            int base = (blk << lm) + j;
            int i0 = skew(base);
            int i1 = skew(base + q);
            int i2 = skew(base + 2 * q);
            int i3 = skew(base + 3 * q);
            float2 a0 = data[i0], a1 = data[i1], a2 = data[i2], a3 = data[i3];

            float2 t0 = cadd(a0, a2), t1 = csub(a0, a2);
            float2 t2 = cadd(a1, a3), t3 = csub(a1, a3);
            float2 y0 = cadd(t0, t2);
            float2 y2 = csub(t0, t2);
            float2 y1 = make_float2(t1.x + t3.y, t1.y - t3.x);   // t1 - i*t3
            float2 y3 = make_float2(t1.x - t3.y, t1.y + t3.x);   // t1 + i*t3

            float2 w1 = tw[skew(j << tsh)];        // W_N^{j*N/m}
            float2 w2 = cmul(w1, w1);
            float2 w3 = cmul(w2, w1);

            data[i0] = y0;
            data[i1] = cmul(y1, w1);
            data[i2] = cmul(y2, w2);
            data[i3] = cmul(y3, w3);
        }
        __syncthreads();
    }
}

// Inverse radix-4 DIT (conjugate twiddles, unscaled): digit-reversed -> natural.
__device__ __forceinline__ void fft_inv(float2* data, const float2* tw, int tid)
{
    for (int lm = 2; lm <= 14; lm += 2) {
        const int qsh = lm - 2;
        const int q   = 1 << qsh;
        const int tsh = 14 - lm;
        #pragma unroll 4
        for (int r = 0; r < BF_PER_THR; r++) {
            int t    = tid + NTHREADS * r;
            int j    = t & (q - 1);
            int blk  = t >> qsh;
            int base = (blk << lm) + j;
            int i0 = skew(base);
            int i1 = skew(base + q);
            int i2 = skew(base + 2 * q);
            int i3 = skew(base + 3 * q);
            float2 c0 = data[i0], c1 = data[i1], c2 = data[i2], c3 = data[i3];

            float2 w1 = tw[skew(j << tsh)];
            float2 w2 = cmul(w1, w1);
            float2 w3 = cmul(w2, w1);
            c1 = cmulc(c1, w1);
            c2 = cmulc(c2, w2);
            c3 = cmulc(c3, w3);

            float2 u0 = cadd(c0, c2), u1 = csub(c0, c2);
            float2 u2 = cadd(c1, c3), u3 = csub(c1, c3);
            float2 a0 = cadd(u0, u2);
            float2 a2 = csub(u0, u2);
            float2 a1 = make_float2(u1.x - u3.y, u1.y + u3.x);   // u1 + i*u3
            float2 a3 = make_float2(u1.x + u3.y, u1.y - u3.x);   // u1 - i*u3

            data[i0] = a0;
            data[i1] = a1;
            data[i2] = a2;
            data[i3] = a3;
        }
        __syncthreads();
    }
}

__global__ void __launch_bounds__(NTHREADS, 1)
fftconv_kernel(const float* __restrict__ X,
               const float* __restrict__ H,
               float* __restrict__ Y)
{
    extern __shared__ float2 smem_f2[];
    float2* data = smem_f2;                    // skewed, DATA_SKEW_SIZE
    float2* tw   = smem_f2 + DATA_SKEW_SIZE;   // skewed, TW_SKEW_SIZE

    const int tid = threadIdx.x;
    const size_t row = blockIdx.x;

    // Twiddle table: tw[j] = exp(-2*pi*i*j/N), j in [0, N/2)
    for (int j = tid; j < FFT_N / 2; j += NTHREADS) {
        float s, c;
        sincospif(-(float)j * (1.0f / 8192.0f), &s, &c);
        tw[skew(j)] = make_float2(c, s);
    }

    // ---- filter row (zero-padded) ----
    const float* hr = H + row * SEQ_L;
    for (int t = tid; t < SEQ_L; t += NTHREADS)
        data[skew(t)] = make_float2(hr[t], 0.0f);
    for (int t = SEQ_L + tid; t < FFT_N; t += NTHREADS)
        data[skew(t)] = make_float2(0.0f, 0.0f);
    __syncthreads();   // also fences twiddle table

    fft_fwd(data, tw, tid);   // ends with syncthreads

    // Stash H spectrum (digit-reversed order) in registers.
    float2 Hs[FFT_N / NTHREADS];
    #pragma unroll
    for (int r = 0; r < FFT_N / NTHREADS; r++)
        Hs[r] = data[skew(tid + NTHREADS * r)];
    __syncthreads();

    // ---- input row (zero-padded) ----
    const float* xr = X + row * SEQ_L;
    for (int t = tid; t < SEQ_L; t += NTHREADS)
        data[skew(t)] = make_float2(xr[t], 0.0f);
    for (int t = SEQ_L + tid; t < FFT_N; t += NTHREADS)
        data[skew(t)] = make_float2(0.0f, 0.0f);
    __syncthreads();

    fft_fwd(data, tw, tid);

    // Pointwise product in digit-reversed domain, with 1/N^2 scale.
    const float sc = 1.0f / ((float)FFT_N * (float)FFT_N);
    #pragma unroll
    for (int r = 0; r < FFT_N / NTHREADS; r++) {
        int p = skew(tid + NTHREADS * r);
        float2 pr = cmul(data[p], Hs[r]);
        data[p] = make_float2(pr.x * sc, pr.y * sc);
    }
    __syncthreads();

    fft_inv(data, tw, tid);   // ends with syncthreads

    // First L real parts, natural order, coalesced.
    float* yr = Y + row * SEQ_L;
    for (int t = tid; t < SEQ_L; t += NTHREADS)
        yr[t] = data[skew(t)].x;
}

extern "C" void kernel_launch(void* const* d_in, const int* in_sizes, int n_in,
                              void* d_out, int out_size)
{
    const float* x = (const float*)d_in[0];   // inputs  [B, L] fp32
    const float* h = (const float*)d_in[1];   // filters [B, L] fp32
    float* y = (float*)d_out;                 // [B, L] fp32

    int B = in_sizes[0] / SEQ_L;

    cudaFuncSetAttribute(fftconv_kernel,
                         cudaFuncAttributeMaxDynamicSharedMemorySize, SMEM_BYTES);
    fftconv_kernel<<<B, NTHREADS, SMEM_BYTES>>>(x, h, y);
}

// round 4
// speedup vs baseline: 3.4706x; 3.4706x over previous
#include <cuda_runtime.h>
#include <cuda_bf16.h>

// FFT long convolution: y[b,0:L] = (1/(2L)) * linear_conv(x[b], h[b]),
// B=4096, L=8192, N=16384-point FFT per row, one CTA per row, all in SMEM.
//
//  - pack z = x + i*h, ONE forward FFT (radix-4 DIF, natural -> base-4
//    digit-reversed), Hermitian-pair pointwise product in scrambled domain,
//    ONE inverse FFT (radix-4 DIT) -> natural order, take real part.
//  - stages fused in pairs (radix-16 in registers): 4 SMEM rounds per FFT.
//  - first fwd round reads straight from global (upper half = implicit zeros);
//    last inv round writes y straight to global (only low half, real parts).
//  - twiddle table: 1024 entries (W_N^j, j < N/16); higher twiddles derived
//    via compile-time W16 constants.

#define FFT_N    16384
#define SEQ_L    8192
#define NTHREADS 512

__device__ __forceinline__ int skew(int i) {
    return i + (i >> 4) + (i >> 8) + (i >> 12);
}
#define DATA_SKEW_SIZE 17473   // skew(16383)+1
#define TW_SKEW_SIZE   1090    // skew(1023)+1
#define SMEM_BYTES ((DATA_SKEW_SIZE + TW_SKEW_SIZE) * (int)sizeof(float2))

__device__ __forceinline__ float2 cadd(float2 a, float2 b) { return make_float2(a.x + b.x, a.y + b.y); }
__device__ __forceinline__ float2 csub(float2 a, float2 b) { return make_float2(a.x - b.x, a.y - b.y); }
__device__ __forceinline__ float2 cmul(float2 a, float2 b) {
    return make_float2(fmaf(a.x, b.x, -(a.y * b.y)), fmaf(a.x, b.y, a.y * b.x));
}
// a * conj(b)
__device__ __forceinline__ float2 cmulc(float2 a, float2 b) {
    return make_float2(fmaf(a.x, b.x, a.y * b.y), fmaf(a.y, b.x, -(a.x * b.y)));
}

// W16^t = exp(-i*pi*t/8)
#define W16_1 make_float2( 0.92387953251128674f, -0.38268343236508978f)
#define W16_2 make_float2( 0.70710678118654752f, -0.70710678118654752f)
#define W16_3 make_float2( 0.38268343236508978f, -0.92387953251128674f)
#define W16_4 make_float2( 0.0f,                 -1.0f)
#define W16_6 make_float2(-0.70710678118654752f, -0.70710678118654752f)
#define W16_9 make_float2(-0.92387953251128674f,  0.38268343236508978f)

__device__ __forceinline__ void bf4_fwd(float2& x0, float2& x1, float2& x2, float2& x3) {
    float2 t0 = cadd(x0, x2), t1 = csub(x0, x2);
    float2 t2 = cadd(x1, x3), t3 = csub(x1, x3);
    x0 = cadd(t0, t2);
    x2 = csub(t0, t2);
    x1 = make_float2(t1.x + t3.y, t1.y - t3.x);   // t1 - i*t3
    x3 = make_float2(t1.x - t3.y, t1.y + t3.x);   // t1 + i*t3
}
__device__ __forceinline__ void bf4_inv(float2& x0, float2& x1, float2& x2, float2& x3) {
    float2 t0 = cadd(x0, x2), t1 = csub(x0, x2);
    float2 t2 = cadd(x1, x3), t3 = csub(x1, x3);
    x0 = cadd(t0, t2);
    x2 = csub(t0, t2);
    x1 = make_float2(t1.x - t3.y, t1.y + t3.x);   // t1 + i*t3
    x3 = make_float2(t1.x + t3.y, t1.y - t3.x);   // t1 - i*t3
}

// base-4 digit reversal of 7 digits (14 bits)
__device__ __forceinline__ int dr4(int p) {
    unsigned r = __brev((unsigned)p) >> 18;
    return (int)(((r & 0x2AAAu) >> 1) | ((r & 0x1555u) << 1));
}

// ---- round 1 forward (stages m=2^14, 2^12), fused global load, top half zero
__device__ __forceinline__ void fwd_round1(const float* __restrict__ xr,
                                           const float* __restrict__ hr,
                                           float2* data, const float2* tw, int tid)
{
    #pragma unroll 1
    for (int rep = 0; rep < 2; rep++) {
        int u = tid + NTHREADS * rep;           // base = u, q2 = 1024
        float2 v[16];
        #pragma unroll
        for (int s = 0; s < 8; s++)
            v[s] = make_float2(xr[u + s * 1024], hr[u + s * 1024]);

        float2 w  = tw[skew(u)];                // W_N^u
        float2 w2 = cmul(w, w);
        float2 w3 = cmul(w2, w);
        float2 p1 = cmul(w2, w2);
        float2 p2 = cmul(p1, p1);
        float2 p3 = cmul(p2, p1);

        // stage m=16384 with x2=x3=0: quads {d, d+4, d+8, d+12}
        #pragma unroll
        for (int d = 0; d < 4; d++) {
            float2 a = v[d], b = v[d + 4];
            v[d]      = cadd(a, b);                                 // y0
            v[d + 4]  = make_float2(a.x + b.y, a.y - b.x);          // a - i b
            v[d + 8]  = csub(a, b);                                 // y2
            v[d + 12] = make_float2(a.x - b.y, a.y + b.x);          // a + i b
        }
        v[4]  = cmul(v[4],  w);
        v[8]  = cmul(v[8],  w2);
        v[12] = cmul(v[12], w3);
        v[5]  = cmul(v[5],  cmul(w,  W16_1));
        v[9]  = cmul(v[9],  cmul(w2, W16_2));
        v[13] = cmul(v[13], cmul(w3, W16_3));
        v[6]  = cmul(v[6],  cmul(w,  W16_2));
        v[10] = cmul(v[10], cmul(w2, W16_4));
        v[14] = cmul(v[14], cmul(w3, W16_6));
        v[7]  = cmul(v[7],  cmul(w,  W16_3));
        v[11] = cmul(v[11], cmul(w2, W16_6));
        v[15] = cmul(v[15], cmul(w3, W16_9));

        // stage m=4096
        #pragma unroll
        for (int r = 0; r < 4; r++) {
            bf4_fwd(v[4*r], v[4*r+1], v[4*r+2], v[4*r+3]);
            v[4*r+1] = cmul(v[4*r+1], p1);
            v[4*r+2] = cmul(v[4*r+2], p2);
            v[4*r+3] = cmul(v[4*r+3], p3);
        }

        #pragma unroll
        for (int s = 0; s < 16; s++) data[skew(u + s * 1024)] = v[s];
    }
    __syncthreads();
}

// ---- generic fused forward round: DIF stages at m = 2^LM and m/4
template<int LM>
__device__ __forceinline__ void super_fwd(float2* data, const float2* tw, int tid)
{
    const int q2  = 1 << (LM - 4);
    const int esh = 14 - LM;
    #pragma unroll 1
    for (int rep = 0; rep < 2; rep++) {
        int u    = tid + NTHREADS * rep;
        int j2   = u & (q2 - 1);
        int base = ((u >> (LM - 4)) << LM) + j2;

        float2 v[16];
        #pragma unroll
        for (int s = 0; s < 16; s++) v[s] = data[skew(base + s * q2)];

        float2 w  = tw[skew(j2 << esh)];
        float2 w2 = cmul(w, w);
        float2 w3 = cmul(w2, w);
        float2 p1 = cmul(w2, w2);
        float2 p2 = cmul(p1, p1);
        float2 p3 = cmul(p2, p1);

        bf4_fwd(v[0], v[4], v[8], v[12]);
        v[4]  = cmul(v[4],  w);
        v[8]  = cmul(v[8],  w2);
        v[12] = cmul(v[12], w3);
        bf4_fwd(v[1], v[5], v[9], v[13]);
        v[5]  = cmul(v[5],  cmul(w,  W16_1));
        v[9]  = cmul(v[9],  cmul(w2, W16_2));
        v[13] = cmul(v[13], cmul(w3, W16_3));
        bf4_fwd(v[2], v[6], v[10], v[14]);
        v[6]  = cmul(v[6],  cmul(w,  W16_2));
        v[10] = cmul(v[10], cmul(w2, W16_4));
        v[14] = cmul(v[14], cmul(w3, W16_6));
        bf4_fwd(v[3], v[7], v[11], v[15]);
        v[7]  = cmul(v[7],  cmul(w,  W16_3));
        v[11] = cmul(v[11], cmul(w2, W16_6));
        v[15] = cmul(v[15], cmul(w3, W16_9));

        #pragma unroll
        for (int r = 0; r < 4; r++) {
            bf4_fwd(v[4*r], v[4*r+1], v[4*r+2], v[4*r+3]);
            v[4*r+1] = cmul(v[4*r+1], p1);
            v[4*r+2] = cmul(v[4*r+2], p2);
            v[4*r+3] = cmul(v[4*r+3], p3);
        }

        #pragma unroll
        for (int s = 0; s < 16; s++) data[skew(base + s * q2)] = v[s];
    }
    __syncthreads();
}

// ---- generic fused inverse round: DIT stages at m/4 then m = 2^LM
template<int LM>
__device__ __forceinline__ void super_inv(float2* data, const float2* tw, int tid)
{
    const int q2  = 1 << (LM - 4);
    const int esh = 14 - LM;
    #pragma unroll 1
    for (int rep = 0; rep < 2; rep++) {
        int u    = tid + NTHREADS * rep;
        int j2   = u & (q2 - 1);
        int base = ((u >> (LM - 4)) << LM) + j2;

        float2 v[16];
        #pragma unroll
        for (int s = 0; s < 16; s++) v[s] = data[skew(base + s * q2)];

        float2 w  = tw[skew(j2 << esh)];
        float2 w2 = cmul(w, w);
        float2 w3 = cmul(w2, w);
        float2 p1 = cmul(w2, w2);
        float2 p2 = cmul(p1, p1);
        float2 p3 = cmul(p2, p1);

        #pragma unroll
        for (int r = 0; r < 4; r++) {
            v[4*r+1] = cmulc(v[4*r+1], p1);
            v[4*r+2] = cmulc(v[4*r+2], p2);
            v[4*r+3] = cmulc(v[4*r+3], p3);
            bf4_inv(v[4*r], v[4*r+1], v[4*r+2], v[4*r+3]);
        }

        v[4]  = cmulc(v[4],  w);
        v[8]  = cmulc(v[8],  w2);
        v[12] = cmulc(v[12], w3);
        bf4_inv(v[0], v[4], v[8], v[12]);
        v[5]  = cmulc(v[5],  cmul(w,  W16_1));
        v[9]  = cmulc(v[9],  cmul(w2, W16_2));
        v[13] = cmulc(v[13], cmul(w3, W16_3));
        bf4_inv(v[1], v[5], v[9], v[13]);
        v[6]  = cmulc(v[6],  cmul(w,  W16_2));
        v[10] = cmulc(v[10], cmul(w2, W16_4));
        v[14] = cmulc(v[14], cmul(w3, W16_6));
        bf4_inv(v[2], v[6], v[10], v[14]);
        v[7]  = cmulc(v[7],  cmul(w,  W16_3));
        v[11] = cmulc(v[11], cmul(w2, W16_6));
        v[15] = cmulc(v[15], cmul(w3, W16_9));
        bf4_inv(v[3], v[7], v[11], v[15]);

        #pragma unroll
        for (int s = 0; s < 16; s++) data[skew(base + s * q2)] = v[s];
    }
    __syncthreads();
}

// ---- last inverse round (stages m/4=2^12 then m=2^14), fused global store.
// Outputs land in natural order at u + s*1024; only s<8 real parts needed.
__device__ __forceinline__ void inv_round_last(float2* data, const float2* tw,
                                               float* __restrict__ yr, int tid)
{
    #pragma unroll 1
    for (int rep = 0; rep < 2; rep++) {
        int u = tid + NTHREADS * rep;           // base = u, q2 = 1024
        float2 v[16];
        #pragma unroll
        for (int s = 0; s < 16; s++) v[s] = data[skew(u + s * 1024)];

        float2 w  = tw[skew(u)];
        float2 w2 = cmul(w, w);
        float2 w3 = cmul(w2, w);
        float2 p1 = cmul(w2, w2);
        float2 p2 = cmul(p1, p1);
        float2 p3 = cmul(p2, p1);

        // undo stage m/4 = 4096
        #pragma unroll
        for (int r = 0; r < 4; r++) {
            v[4*r+1] = cmulc(v[4*r+1], p1);
            v[4*r+2] = cmulc(v[4*r+2], p2);
            v[4*r+3] = cmulc(v[4*r+3], p3);
            bf4_inv(v[4*r], v[4*r+1], v[4*r+2], v[4*r+3]);
        }

        // undo stage m = 16384, but only outputs 0..7 (low half) are kept.
        // inverse twiddles on groups 4..15:
        v[4]  = cmulc(v[4],  w);
        v[8]  = cmulc(v[8],  w2);
        v[12] = cmulc(v[12], w3);
        v[5]  = cmulc(v[5],  cmul(w,  W16_1));
        v[9]  = cmulc(v[9],  cmul(w2, W16_2));
        v[13] = cmulc(v[13], cmul(w3, W16_3));
        v[6]  = cmulc(v[6],  cmul(w,  W16_2));
        v[10] = cmulc(v[10], cmul(w2, W16_4));
        v[14] = cmulc(v[14], cmul(w3, W16_6));
        v[7]  = cmulc(v[7],  cmul(w,  W16_3));
        v[11] = cmulc(v[11], cmul(w2, W16_6));
        v[15] = cmulc(v[15], cmul(w3, W16_9));

        #pragma unroll
        for (int d = 0; d < 4; d++) {
            float2 c0 = v[d], c1 = v[d+4], c2 = v[d+8], c3 = v[d+12];
            // out0 = (c0+c2) + (c1+c3); out1 = (c0-c2) + i*(c1-c3)
            float out0_re = (c0.x + c2.x) + (c1.x + c3.x);
            float out1_re = (c0.x - c2.x) - (c1.y - c3.y);
            yr[u + d * 1024]       = out0_re;
            yr[u + (d + 4) * 1024] = out1_re;
        }
    }
}

__global__ void __launch_bounds__(NTHREADS, 1)
fftconv_kernel(const float* __restrict__ X,
               const float* __restrict__ H,
               float* __restrict__ Y)
{
    extern __shared__ float2 smem_f2[];
    float2* data = smem_f2;
    float2* tw   = smem_f2 + DATA_SKEW_SIZE;

    const int tid = threadIdx.x;
    const size_t row = blockIdx.x;

    // twiddle table: W_N^j, j < 1024
    for (int j = tid; j < 1024; j += NTHREADS) {
        float s, c;
        sincospif(-(float)j * (1.0f / 8192.0f), &s, &c);
        tw[skew(j)] = make_float2(c, s);
    }
    __syncthreads();

    const float* xr = X + row * SEQ_L;
    const float* hr = H + row * SEQ_L;

    // forward FFT: natural -> base-4 digit-reversed (stages 14,12 | 10,8 | 6,4 | 2)
    fwd_round1(xr, hr, data, tw, tid);
    super_fwd<10>(data, tw, tid);
    super_fwd<6> (data, tw, tid);

    // m=4 stage (no twiddles)
    #pragma unroll 1
    for (int rep = 0; rep < 8; rep++) {
        int b = tid + NTHREADS * rep;
        int i0 = skew(4 * b);                  // 4b..4b+3 stay in one 16-block
        float2 x0 = data[i0], x1 = data[i0+1], x2 = data[i0+2], x3 = data[i0+3];
        bf4_fwd(x0, x1, x2, x3);
        data[i0] = x0; data[i0+1] = x1; data[i0+2] = x2; data[i0+3] = x3;
    }
    __syncthreads();

    // Hermitian-pair pointwise product in scrambled domain:
    // P[k] = X[k]*H[k] = (Z[k]^2 - conj(Z[-k])^2) / (4i), scaled by 1/N^2.
    {
        const float c = 0.25f / ((float)FFT_N * (float)FFT_N);
        #pragma unroll 1
        for (int rep = 0; rep < FFT_N / NTHREADS; rep++) {
            int p  = tid + NTHREADS * rep;
            int k  = dr4(p);
            int p2 = dr4((FFT_N - k) & (FFT_N - 1));
            if (p2 < p) continue;              // pair owned by smaller index
            float2 a = data[skew(p)];
            float2 b = data[skew(p2)];
            float Ax = a.x * a.x - a.y * a.y, Ay = 2.0f * a.x * a.y;
            float Bx = b.x * b.x - b.y * b.y, By = 2.0f * b.x * b.y;
            float px = (Ay + By) * c;
            float py = (Bx - Ax) * c;
            data[skew(p)]  = make_float2(px,  py);
            data[skew(p2)] = make_float2(px, -py);
        }
    }
    __syncthreads();

    // inverse FFT: digit-reversed -> natural (stages 2 | 4,6 | 8,10 | 12,14)
    #pragma unroll 1
    for (int rep = 0; rep < 8; rep++) {
        int b = tid + NTHREADS * rep;
        int i0 = skew(4 * b);
        float2 x0 = data[i0], x1 = data[i0+1], x2 = data[i0+2], x3 = data[i0+3];
        bf4_inv(x0, x1, x2, x3);
        data[i0] = x0; data[i0+1] = x1; data[i0+2] = x2; data[i0+3] = x3;
    }
    __syncthreads();

    super_inv<6> (data, tw, tid);
    super_inv<10>(data, tw, tid);
    inv_round_last(data, tw, Y + row * SEQ_L, tid);
}

extern "C" void kernel_launch(void* const* d_in, const int* in_sizes, int n_in,
                              void* d_out, int out_size)
{
    const float* x = (const float*)d_in[0];
    const float* h = (const float*)d_in[1];
    float* y = (float*)d_out;

    int B = in_sizes[0] / SEQ_L;

    cudaFuncSetAttribute(fftconv_kernel,
                         cudaFuncAttributeMaxDynamicSharedMemorySize, SMEM_BYTES);
    fftconv_kernel<<<B, NTHREADS, SMEM_BYTES>>>(x, h, y);
}

// round 6
// speedup vs baseline: 4.4463x; 1.2811x over previous
#include <cuda_runtime.h>
#include <cuda_bf16.h>

// FFT long convolution: y[b,0:L] = (1/(2L)) * linear_conv(x[b], h[b]),
// B=4096, L=8192, N=16384-point FFT per row, one CTA per row, all in SMEM.
//
//  - pack z = x + i*h, one fwd FFT (radix-4 DIF -> base-4 digit-reversed),
//    Hermitian-pair pointwise product in scrambled domain, one inv FFT.
//  - radix-16 fused rounds (two radix-4 stages in registers).
//  - first fwd round reads straight from global (upper half implicit zeros);
//    last inv round writes y straight to global (low half real parts only).
//  - m=4 fwd stage + pointwise + m=4 inv stage fused into ONE smem round
//    (quad-level Hermitian pairing: quad b <-> quad b' = dr4(N - dr4(4b))>>2,
//     t <-> 3-t).
//  - skew addressing strength-reduced: skew(base + s*q2) = skew(base) +
//    skew(s*q2) [bit-fields disjoint, carry-free], so per-access cost is an
//    LDS/STS immediate offset.

#define FFT_N    16384
#define SEQ_L    8192
#define NTHREADS 512

__device__ __forceinline__ int skew(int i) {
    return i + (i >> 4) + (i >> 8) + (i >> 12);
}
#define DATA_SKEW_SIZE 17473   // skew(16383)+1
#define TW_SKEW_SIZE   1090    // skew(1023)+1
#define SMEM_BYTES ((DATA_SKEW_SIZE + TW_SKEW_SIZE) * (int)sizeof(float2))

__device__ __forceinline__ float2 cadd(float2 a, float2 b) { return make_float2(a.x + b.x, a.y + b.y); }
__device__ __forceinline__ float2 csub(float2 a, float2 b) { return make_float2(a.x - b.x, a.y - b.y); }
__device__ __forceinline__ float2 cmul(float2 a, float2 b) {
    return make_float2(fmaf(a.x, b.x, -(a.y * b.y)), fmaf(a.x, b.y, a.y * b.x));
}
// a * conj(b)
__device__ __forceinline__ float2 cmulc(float2 a, float2 b) {
    return make_float2(fmaf(a.x, b.x, a.y * b.y), fmaf(a.y, b.x, -(a.x * b.y)));
}

// W16^t = exp(-i*pi*t/8)
#define W16_1 make_float2( 0.92387953251128674f, -0.38268343236508978f)
#define W16_2 make_float2( 0.70710678118654752f, -0.70710678118654752f)
#define W16_3 make_float2( 0.38268343236508978f, -0.92387953251128674f)
#define W16_4 make_float2( 0.0f,                 -1.0f)
#define W16_6 make_float2(-0.70710678118654752f, -0.70710678118654752f)
#define W16_9 make_float2(-0.92387953251128674f,  0.38268343236508978f)

__device__ __forceinline__ void bf4_fwd(float2& x0, float2& x1, float2& x2, float2& x3) {
    float2 t0 = cadd(x0, x2), t1 = csub(x0, x2);
    float2 t2 = cadd(x1, x3), t3 = csub(x1, x3);
    x0 = cadd(t0, t2);
    x2 = csub(t0, t2);
    x1 = make_float2(t1.x + t3.y, t1.y - t3.x);   // t1 - i*t3
    x3 = make_float2(t1.x - t3.y, t1.y + t3.x);   // t1 + i*t3
}
__device__ __forceinline__ void bf4_inv(float2& x0, float2& x1, float2& x2, float2& x3) {
    float2 t0 = cadd(x0, x2), t1 = csub(x0, x2);
    float2 t2 = cadd(x1, x3), t3 = csub(x1, x3);
    x0 = cadd(t0, t2);
    x2 = csub(t0, t2);
    x1 = make_float2(t1.x - t3.y, t1.y + t3.x);   // t1 + i*t3
    x3 = make_float2(t1.x + t3.y, t1.y - t3.x);   // t1 - i*t3
}

// base-4 digit reversal of 7 digits (14 bits); involution
__device__ __forceinline__ int dr4(int p) {
    unsigned r = __brev((unsigned)p) >> 18;
    return (int)(((r & 0x2AAAu) >> 1) | ((r & 0x1555u) << 1));
}

// ---- round 1 forward (stages m=2^14, 2^12), fused global load, top half zero
__device__ __forceinline__ void fwd_round1(const float* __restrict__ xr,
                                           const float* __restrict__ hr,
                                           float2* data, const float2* tw, int tid)
{
    #pragma unroll 1
    for (int rep = 0; rep < 2; rep++) {
        int u = tid + NTHREADS * rep;           // base = u, q2 = 1024
        float2 v[16];
        #pragma unroll
        for (int s = 0; s < 8; s++)
            v[s] = make_float2(xr[u + s * 1024], hr[u + s * 1024]);

        float2 w  = tw[skew(u)];                // W_N^u
        float2 w2 = cmul(w, w);
        float2 w3 = cmul(w2, w);
        float2 p1 = cmul(w2, w2);
        float2 p2 = cmul(p1, p1);
        float2 p3 = cmul(p2, p1);

        // stage m=16384 with x2=x3=0
        #pragma unroll
        for (int d = 0; d < 4; d++) {
            float2 a = v[d], b = v[d + 4];
            v[d]      = cadd(a, b);
            v[d + 4]  = make_float2(a.x + b.y, a.y - b.x);  // a - i b
            v[d + 8]  = csub(a, b);
            v[d + 12] = make_float2(a.x - b.y, a.y + b.x);  // a + i b
        }
        v[4]  = cmul(v[4],  w);
        v[8]  = cmul(v[8],  w2);
        v[12] = cmul(v[12], w3);
        v[5]  = cmul(v[5],  cmul(w,  W16_1));
        v[9]  = cmul(v[9],  cmul(w2, W16_2));
        v[13] = cmul(v[13], cmul(w3, W16_3));
        v[6]  = cmul(v[6],  cmul(w,  W16_2));
        v[10] = cmul(v[10], cmul(w2, W16_4));
        v[14] = cmul(v[14], cmul(w3, W16_6));
        v[7]  = cmul(v[7],  cmul(w,  W16_3));
        v[11] = cmul(v[11], cmul(w2, W16_6));
        v[15] = cmul(v[15], cmul(w3, W16_9));

        // stage m=4096
        #pragma unroll
        for (int r = 0; r < 4; r++) {
            bf4_fwd(v[4*r], v[4*r+1], v[4*r+2], v[4*r+3]);
            v[4*r+1] = cmul(v[4*r+1], p1);
            v[4*r+2] = cmul(v[4*r+2], p2);
            v[4*r+3] = cmul(v[4*r+3], p3);
        }

        float2* dptr = data + skew(u);          // strength-reduced skew
        #pragma unroll
        for (int s = 0; s < 16; s++) dptr[skew(s * 1024)] = v[s];
    }
    __syncthreads();
}

// ---- generic fused forward round: DIF stages at m = 2^LM and m/4
template<int LM>
__device__ __forceinline__ void super_fwd(float2* data, const float2* tw, int tid)
{
    const int q2  = 1 << (LM - 4);
    const int esh = 14 - LM;
    #pragma unroll 1
    for (int rep = 0; rep < 2; rep++) {
        int u    = tid + NTHREADS * rep;
        int j2   = u & (q2 - 1);
        int base = ((u >> (LM - 4)) << LM) + j2;
        float2* dptr = data + skew(base);       // skew(base + s*q2) = skew(base) + skew(s*q2)

        float2 v[16];
        #pragma unroll
        for (int s = 0; s < 16; s++) v[s] = dptr[skew(s * q2)];

        float2 w  = tw[skew(j2 << esh)];
        float2 w2 = cmul(w, w);
        float2 w3 = cmul(w2, w);
        float2 p1 = cmul(w2, w2);
        float2 p2 = cmul(p1, p1);
        float2 p3 = cmul(p2, p1);

        bf4_fwd(v[0], v[4], v[8], v[12]);
        v[4]  = cmul(v[4],  w);
        v[8]  = cmul(v[8],  w2);
        v[12] = cmul(v[12], w3);
        bf4_fwd(v[1], v[5], v[9], v[13]);
        v[5]  = cmul(v[5],  cmul(w,  W16_1));
        v[9]  = cmul(v[9],  cmul(w2, W16_2));
        v[13] = cmul(v[13], cmul(w3, W16_3));
        bf4_fwd(v[2], v[6], v[10], v[14]);
        v[6]  = cmul(v[6],  cmul(w,  W16_2));
        v[10] = cmul(v[10], cmul(w2, W16_4));
        v[14] = cmul(v[14], cmul(w3, W16_6));
        bf4_fwd(v[3], v[7], v[11], v[15]);
        v[7]  = cmul(v[7],  cmul(w,  W16_3));
        v[11] = cmul(v[11], cmul(w2, W16_6));
        v[15] = cmul(v[15], cmul(w3, W16_9));

        #pragma unroll
        for (int r = 0; r < 4; r++) {
            bf4_fwd(v[4*r], v[4*r+1], v[4*r+2], v[4*r+3]);
            v[4*r+1] = cmul(v[4*r+1], p1);
            v[4*r+2] = cmul(v[4*r+2], p2);
            v[4*r+3] = cmul(v[4*r+3], p3);
        }

        #pragma unroll
        for (int s = 0; s < 16; s++) dptr[skew(s * q2)] = v[s];
    }
    __syncthreads();
}

// ---- generic fused inverse round: DIT stages at m/4 then m = 2^LM
template<int LM>
__device__ __forceinline__ void super_inv(float2* data, const float2* tw, int tid)
{
    const int q2  = 1 << (LM - 4);
    const int esh = 14 - LM;
    #pragma unroll 1
    for (int rep = 0; rep < 2; rep++) {
        int u    = tid + NTHREADS * rep;
        int j2   = u & (q2 - 1);
        int base = ((u >> (LM - 4)) << LM) + j2;
        float2* dptr = data + skew(base);

        float2 v[16];
        #pragma unroll
        for (int s = 0; s < 16; s++) v[s] = dptr[skew(s * q2)];

        float2 w  = tw[skew(j2 << esh)];
        float2 w2 = cmul(w, w);
        float2 w3 = cmul(w2, w);
        float2 p1 = cmul(w2, w2);
        float2 p2 = cmul(p1, p1);
        float2 p3 = cmul(p2, p1);

        #pragma unroll
        for (int r = 0; r < 4; r++) {
            v[4*r+1] = cmulc(v[4*r+1], p1);
            v[4*r+2] = cmulc(v[4*r+2], p2);
            v[4*r+3] = cmulc(v[4*r+3], p3);
            bf4_inv(v[4*r], v[4*r+1], v[4*r+2], v[4*r+3]);
        }

        v[4]  = cmulc(v[4],  w);
        v[8]  = cmulc(v[8],  w2);
        v[12] = cmulc(v[12], w3);
        bf4_inv(v[0], v[4], v[8], v[12]);
        v[5]  = cmulc(v[5],  cmul(w,  W16_1));
        v[9]  = cmulc(v[9],  cmul(w2, W16_2));
        v[13] = cmulc(v[13], cmul(w3, W16_3));
        bf4_inv(v[1], v[5], v[9], v[13]);
        v[6]  = cmulc(v[6],  cmul(w,  W16_2));
        v[10] = cmulc(v[10], cmul(w2, W16_4));
        v[14] = cmulc(v[14], cmul(w3, W16_6));
        bf4_inv(v[2], v[6], v[10], v[14]);
        v[7]  = cmulc(v[7],  cmul(w,  W16_3));
        v[11] = cmulc(v[11], cmul(w2, W16_6));
        v[15] = cmulc(v[15], cmul(w3, W16_9));
        bf4_inv(v[3], v[7], v[11], v[15]);

        #pragma unroll
        for (int s = 0; s < 16; s++) dptr[skew(s * q2)] = v[s];
    }
    __syncthreads();
}

// ---- pointwise pair core: a = Z[k], b = Z[-k] -> P[k], P[-k] with scale c
__device__ __forceinline__ void pw_pair(float2& a, float2& b, float c) {
    float2 A = a, B = b;
    float Ax = A.x * A.x - A.y * A.y, Ay = 2.0f * A.x * A.y;
    float Bx = B.x * B.x - B.y * B.y, By = 2.0f * B.x * B.y;
    float px = (Ay + By) * c;
    float py = (Bx - Ax) * c;
    a = make_float2(px,  py);
    b = make_float2(px, -py);
}

// ---- fused middle round: fwd m=4 stage + pointwise + inv m=4 stage.
// Quad b (points 4b+t = Z[rb + 4096 t], rb = dr4(4b)) pairs with quad
// bp = dr4(16384 - rb) >> 2 via t <-> 3-t.  b=0 special: (0,0),(1,3),(2,2).
__device__ __forceinline__ void middle_round(float2* data, int tid)
{
    const float c = 0.25f / ((float)FFT_N * (float)FFT_N);
    #pragma unroll 1
    for (int rep = 0; rep < 8; rep++) {
        int b  = tid + NTHREADS * rep;          // quad index
        int rb = dr4(4 * b);
        int bp = (b == 0) ? 0 : (dr4(16384 - rb) >> 2);
        if (bp < b) continue;                   // pair owned by smaller quad

        int ia = skew(4 * b);                   // quad contiguous: ia..ia+3
        float2 a0 = data[ia], a1 = data[ia+1], a2 = data[ia+2], a3 = data[ia+3];
        bf4_fwd(a0, a1, a2, a3);

        if (bp == b) {
            if (b == 0) {
                pw_pair(a0, a0, c);             // k=0 self
                pw_pair(a1, a3, c);             // 4096 <-> 12288
                pw_pair(a2, a2, c);             // Nyquist self
            } else {
                pw_pair(a0, a3, c);
                pw_pair(a1, a2, c);
            }
            bf4_inv(a0, a1, a2, a3);
            data[ia] = a0; data[ia+1] = a1; data[ia+2] = a2; data[ia+3] = a3;
        } else {
            int ib = skew(4 * bp);
            float2 b0 = data[ib], b1 = data[ib+1], b2 = data[ib+2], b3 = data[ib+3];
            bf4_fwd(b0, b1, b2, b3);

            pw_pair(a0, b3, c);
            pw_pair(a1, b2, c);
            pw_pair(a2, b1, c);
            pw_pair(a3, b0, c);

            bf4_inv(a0, a1, a2, a3);
            bf4_inv(b0, b1, b2, b3);
            data[ia] = a0; data[ia+1] = a1; data[ia+2] = a2; data[ia+3] = a3;
            data[ib] = b0; data[ib+1] = b1; data[ib+2] = b2; data[ib+3] = b3;
        }
    }
    __syncthreads();
}

// ---- last inverse round (stages 2^12 then 2^14), fused global store.
__device__ __forceinline__ void inv_round_last(float2* data, const float2* tw,
                                               float* __restrict__ yr, int tid)
{
    #pragma unroll 1
    for (int rep = 0; rep < 2; rep++) {
        int u = tid + NTHREADS * rep;           // base = u, q2 = 1024
        float2* dptr = data + skew(u);
        float2 v[16];
        #pragma unroll
        for (int s = 0; s < 16; s++) v[s] = dptr[skew(s * 1024)];

        float2 w  = tw[skew(u)];
        float2 w2 = cmul(w, w);
        float2 w3 = cmul(w2, w);
        float2 p1 = cmul(w2, w2);
        float2 p2 = cmul(p1, p1);
        float2 p3 = cmul(p2, p1);

        // undo stage m/4 = 4096
        #pragma unroll
        for (int r = 0; r < 4; r++) {
            v[4*r+1] = cmulc(v[4*r+1], p1);
            v[4*r+2] = cmulc(v[4*r+2], p2);
            v[4*r+3] = cmulc(v[4*r+3], p3);
            bf4_inv(v[4*r], v[4*r+1], v[4*r+2], v[4*r+3]);
        }

        // undo stage m = 16384; only low-half real parts are kept.
        v[4]  = cmulc(v[4],  w);
        v[8]  = cmulc(v[8],  w2);
        v[12] = cmulc(v[12], w3);
        v[5]  = cmulc(v[5],  cmul(w,  W16_1));
        v[9]  = cmulc(v[9],  cmul(w2, W16_2));
        v[13] = cmulc(v[13], cmul(w3, W16_3));
        v[6]  = cmulc(v[6],  cmul(w,  W16_2));
        v[10] = cmulc(v[10], cmul(w2, W16_4));
        v[14] = cmulc(v[14], cmul(w3, W16_6));
        v[7]  = cmulc(v[7],  cmul(w,  W16_3));
        v[11] = cmulc(v[11], cmul(w2, W16_6));
        v[15] = cmulc(v[15], cmul(w3, W16_9));

        #pragma unroll
        for (int d = 0; d < 4; d++) {
            float2 c0 = v[d], c1 = v[d+4], c2 = v[d+8], c3 = v[d+12];
            float out0_re = (c0.x + c2.x) + (c1.x + c3.x);
            float out1_re = (c0.x - c2.x) - (c1.y - c3.y);
            yr[u + d * 1024]       = out0_re;
            yr[u + (d + 4) * 1024] = out1_re;
        }
    }
}

__global__ void __launch_bounds__(NTHREADS, 1)
fftconv_kernel(const float* __restrict__ X,
               const float* __restrict__ H,
               float* __restrict__ Y)
{
    extern __shared__ float2 smem_f2[];
    float2* data = smem_f2;
    float2* tw   = smem_f2 + DATA_SKEW_SIZE;

    const int tid = threadIdx.x;
    const size_t row = blockIdx.x;

    // twiddle table: W_N^j, j < 1024
    for (int j = tid; j < 1024; j += NTHREADS) {
        float s, c;
        sincospif(-(float)j * (1.0f / 8192.0f), &s, &c);
        tw[skew(j)] = make_float2(c, s);
    }
    __syncthreads();

    const float* xr = X + row * SEQ_L;
    const float* hr = H + row * SEQ_L;

    // forward FFT stages (14,12 | 10,8 | 6,4), fused pointwise (incl. stage 2),
    // inverse FFT stages (4,6 | 8,10 | 12,14)
    fwd_round1(xr, hr, data, tw, tid);
    super_fwd<10>(data, tw, tid);
    super_fwd<6> (data, tw, tid);
    middle_round(data, tid);
    super_inv<6> (data, tw, tid);
    super_inv<10>(data, tw, tid);
    inv_round_last(data, tw, Y + row * SEQ_L, tid);
}

extern "C" void kernel_launch(void* const* d_in, const int* in_sizes, int n_in,
                              void* d_out, int out_size)
{
    const float* x = (const float*)d_in[0];
    const float* h = (const float*)d_in[1];
    float* y = (float*)d_out;

    int B = in_sizes[0] / SEQ_L;

    cudaFuncSetAttribute(fftconv_kernel,
                         cudaFuncAttributeMaxDynamicSharedMemorySize, SMEM_BYTES);
    fftconv_kernel<<<B, NTHREADS, SMEM_BYTES>>>(x, h, y);
}

// round 7
// speedup vs baseline: 4.7324x; 1.0643x over previous
#include <cuda_runtime.h>

// FFT long convolution: y[b,0:L] = (1/(2L)) * linear_conv(x[b], h[b]),
// B=4096, L=8192, N=16384-point FFT per row, one CTA per row, all in SMEM.
//
//  - pack z = x + i*h, one fwd FFT (radix-4 DIF -> base-4 digit-reversed),
//    Hermitian-pair pointwise product in scrambled domain, one inv FFT.
//  - radix-16 fused rounds (two radix-4 stages in registers).
//  - first fwd round reads straight from global; last inv round writes y
//    straight to global (low half real parts only).
//  - fused middle round: m=4 fwd + pointwise + m=4 inv in one SMEM pass.
//  - skew addressing strength-reduced to immediate offsets.
//  - R6: 1024 threads (32 warps, occ 50%) + f32x2 packed butterfly adds.

#define FFT_N    16384
#define SEQ_L    8192
#define NTHREADS 1024

typedef unsigned long long ull;

__device__ __forceinline__ int skew(int i) {
    return i + (i >> 4) + (i >> 8) + (i >> 12);
}
#define DATA_SKEW_SIZE 17473   // skew(16383)+1
#define TW_SKEW_SIZE   1090    // skew(1023)+1
#define SMEM_BYTES ((DATA_SKEW_SIZE + TW_SKEW_SIZE) * (int)sizeof(float2))

// ---------- packed f32x2 helpers ----------
__device__ __forceinline__ ull pk(float x, float y) {
    ull r;
    asm("mov.b64 %0, {%1, %2};" : "=l"(r) : "r"(__float_as_uint(x)), "r"(__float_as_uint(y)));
    return r;
}
__device__ __forceinline__ float2 upk(ull p) {
    unsigned lo, hi;
    asm("mov.b64 {%0, %1}, %2;" : "=r"(lo), "=r"(hi) : "l"(p));
    return make_float2(__uint_as_float(lo), __uint_as_float(hi));
}
__device__ __forceinline__ ull addp(ull a, ull b) {
    ull r; asm("add.rn.f32x2 %0, %1, %2;" : "=l"(r) : "l"(a), "l"(b)); return r;
}
// a - b  ==  fma(b, {-1,-1}, a)   (guaranteed-valid f32x2 form)
__device__ __forceinline__ ull subp(ull a, ull b, ull negone) {
    ull r; asm("fma.rn.f32x2 %0, %1, %2, %3;" : "=l"(r) : "l"(b), "l"(negone), "l"(a)); return r;
}
#define NEGONE2 pk(-1.0f, -1.0f)

// {v.y, -v.x}  (multiply by -i)
__device__ __forceinline__ ull swzn(ull v) {
    float2 f = upk(v);
    return pk(f.y, -f.x);
}

// ---------- scalar complex helpers ----------
__device__ __forceinline__ float2 cmul(float2 a, float2 b) {
    return make_float2(fmaf(a.x, b.x, -(a.y * b.y)), fmaf(a.x, b.y, a.y * b.x));
}
__device__ __forceinline__ float2 cmulc(float2 a, float2 b) {  // a * conj(b)
    return make_float2(fmaf(a.x, b.x, a.y * b.y), fmaf(a.y, b.x, -(a.x * b.y)));
}
__device__ __forceinline__ ull cmul_p(ull a, float2 b) {
    float2 f = upk(a);
    return pk(fmaf(f.x, b.x, -(f.y * b.y)), fmaf(f.x, b.y, f.y * b.x));
}
__device__ __forceinline__ ull cmulc_p(ull a, float2 b) {
    float2 f = upk(a);
    return pk(fmaf(f.x, b.x, f.y * b.y), fmaf(f.y, b.x, -(f.x * b.y)));
}

// W16^t = exp(-i*pi*t/8)
#define W16_1 make_float2( 0.92387953251128674f, -0.38268343236508978f)
#define W16_2 make_float2( 0.70710678118654752f, -0.70710678118654752f)
#define W16_3 make_float2( 0.38268343236508978f, -0.92387953251128674f)
#define W16_4 make_float2( 0.0f,                 -1.0f)
#define W16_6 make_float2(-0.70710678118654752f, -0.70710678118654752f)
#define W16_9 make_float2(-0.92387953251128674f,  0.38268343236508978f)

// packed radix-4 butterflies
__device__ __forceinline__ void bf4_fwd_p(ull& x0, ull& x1, ull& x2, ull& x3, ull n1) {
    ull t0 = addp(x0, x2), t1 = subp(x0, x2, n1);
    ull t2 = addp(x1, x3), t3 = subp(x1, x3, n1);
    x0 = addp(t0, t2);
    x2 = subp(t0, t2, n1);
    ull t3s = swzn(t3);                 // -i*t3
    x1 = addp(t1, t3s);                 // t1 - i t3
    x3 = subp(t1, t3s, n1);             // t1 + i t3
}
__device__ __forceinline__ void bf4_inv_p(ull& x0, ull& x1, ull& x2, ull& x3, ull n1) {
    ull t0 = addp(x0, x2), t1 = subp(x0, x2, n1);
    ull t2 = addp(x1, x3), t3 = subp(x1, x3, n1);
    x0 = addp(t0, t2);
    x2 = subp(t0, t2, n1);
    ull t3s = swzn(t3);
    x1 = subp(t1, t3s, n1);             // t1 + i t3
    x3 = addp(t1, t3s);                 // t1 - i t3
}

// base-4 digit reversal of 7 digits (14 bits); involution
__device__ __forceinline__ int dr4(int p) {
    unsigned r = __brev((unsigned)p) >> 18;
    return (int)(((r & 0x2AAAu) >> 1) | ((r & 0x1555u) << 1));
}

// ---- round 1 forward (stages m=2^14, 2^12), fused global load, top half zero
__device__ __forceinline__ void fwd_round1(const float* __restrict__ xr,
                                           const float* __restrict__ hr,
                                           float2* data, const float2* tw, int tid)
{
    ull n1 = NEGONE2;
    int u = tid;                               // groups = 1024 = NTHREADS
    ull v[16];
    #pragma unroll
    for (int s = 0; s < 8; s++)
        v[s] = pk(xr[u + s * 1024], hr[u + s * 1024]);

    float2 w  = tw[skew(u)];                   // W_N^u
    float2 w2 = cmul(w, w);
    float2 w3 = cmul(w2, w);
    float2 p1 = cmul(w2, w2);
    float2 p2 = cmul(p1, p1);
    float2 p3 = cmul(p2, p1);

    // stage m=16384 with x2=x3=0
    #pragma unroll
    for (int d = 0; d < 4; d++) {
        ull a = v[d], b = v[d + 4];
        ull bs = swzn(b);                      // -i*b
        v[d]      = addp(a, b);
        v[d + 4]  = addp(a, bs);               // a - i b
        v[d + 8]  = subp(a, b, n1);
        v[d + 12] = subp(a, bs, n1);           // a + i b
    }
    v[4]  = cmul_p(v[4],  w);
    v[8]  = cmul_p(v[8],  w2);
    v[12] = cmul_p(v[12], w3);
    v[5]  = cmul_p(v[5],  cmul(w,  W16_1));
    v[9]  = cmul_p(v[9],  cmul(w2, W16_2));
    v[13] = cmul_p(v[13], cmul(w3, W16_3));
    v[6]  = cmul_p(v[6],  cmul(w,  W16_2));
    v[10] = cmul_p(v[10], cmul(w2, W16_4));
    v[14] = cmul_p(v[14], cmul(w3, W16_6));
    v[7]  = cmul_p(v[7],  cmul(w,  W16_3));
    v[11] = cmul_p(v[11], cmul(w2, W16_6));
    v[15] = cmul_p(v[15], cmul(w3, W16_9));

    // stage m=4096
    #pragma unroll
    for (int r = 0; r < 4; r++) {
        bf4_fwd_p(v[4*r], v[4*r+1], v[4*r+2], v[4*r+3], n1);
        v[4*r+1] = cmul_p(v[4*r+1], p1);
        v[4*r+2] = cmul_p(v[4*r+2], p2);
        v[4*r+3] = cmul_p(v[4*r+3], p3);
    }

    ull* dptr = (ull*)(data + skew(u));        // strength-reduced skew
    #pragma unroll
    for (int s = 0; s < 16; s++) dptr[skew(s * 1024)] = v[s];
    __syncthreads();
}

// ---- generic fused forward round: DIF stages at m = 2^LM and m/4
template<int LM>
__device__ __forceinline__ void super_fwd(float2* data, const float2* tw, int tid)
{
    ull n1 = NEGONE2;
    const int q2  = 1 << (LM - 4);
    const int esh = 14 - LM;
    int u    = tid;
    int j2   = u & (q2 - 1);
    int base = ((u >> (LM - 4)) << LM) + j2;
    ull* dptr = (ull*)(data + skew(base));     // skew distributes over disjoint fields

    ull v[16];
    #pragma unroll
    for (int s = 0; s < 16; s++) v[s] = dptr[skew(s * q2)];

    float2 w  = tw[skew(j2 << esh)];
    float2 w2 = cmul(w, w);
    float2 w3 = cmul(w2, w);
    float2 p1 = cmul(w2, w2);
    float2 p2 = cmul(p1, p1);
    float2 p3 = cmul(p2, p1);

    bf4_fwd_p(v[0], v[4], v[8], v[12], n1);
    v[4]  = cmul_p(v[4],  w);
    v[8]  = cmul_p(v[8],  w2);
    v[12] = cmul_p(v[12], w3);
    bf4_fwd_p(v[1], v[5], v[9], v[13], n1);
    v[5]  = cmul_p(v[5],  cmul(w,  W16_1));
    v[9]  = cmul_p(v[9],  cmul(w2, W16_2));
    v[13] = cmul_p(v[13], cmul(w3, W16_3));
    bf4_fwd_p(v[2], v[6], v[10], v[14], n1);
    v[6]  = cmul_p(v[6],  cmul(w,  W16_2));
    v[10] = cmul_p(v[10], cmul(w2, W16_4));
    v[14] = cmul_p(v[14], cmul(w3, W16_6));
    bf4_fwd_p(v[3], v[7], v[11], v[15], n1);
    v[7]  = cmul_p(v[7],  cmul(w,  W16_3));
    v[11] = cmul_p(v[11], cmul(w2, W16_6));
    v[15] = cmul_p(v[15], cmul(w3, W16_9));

    #pragma unroll
    for (int r = 0; r < 4; r++) {
        bf4_fwd_p(v[4*r], v[4*r+1], v[4*r+2], v[4*r+3], n1);
        v[4*r+1] = cmul_p(v[4*r+1], p1);
        v[4*r+2] = cmul_p(v[4*r+2], p2);
        v[4*r+3] = cmul_p(v[4*r+3], p3);
    }

    #pragma unroll
    for (int s = 0; s < 16; s++) dptr[skew(s * q2)] = v[s];
    __syncthreads();
}

// ---- generic fused inverse round: DIT stages at m/4 then m = 2^LM
template<int LM>
__device__ __forceinline__ void super_inv(float2* data, const float2* tw, int tid)
{
    ull n1 = NEGONE2;
    const int q2  = 1 << (LM - 4);
    const int esh = 14 - LM;
    int u    = tid;
    int j2   = u & (q2 - 1);
    int base = ((u >> (LM - 4)) << LM) + j2;
    ull* dptr = (ull*)(data + skew(base));

    ull v[16];
    #pragma unroll
    for (int s = 0; s < 16; s++) v[s] = dptr[skew(s * q2)];

    float2 w  = tw[skew(j2 << esh)];
    float2 w2 = cmul(w, w);
    float2 w3 = cmul(w2, w);
    float2 p1 = cmul(w2, w2);
    float2 p2 = cmul(p1, p1);
    float2 p3 = cmul(p2, p1);

    #pragma unroll
    for (int r = 0; r < 4; r++) {
        v[4*r+1] = cmulc_p(v[4*r+1], p1);
        v[4*r+2] = cmulc_p(v[4*r+2], p2);
        v[4*r+3] = cmulc_p(v[4*r+3], p3);
        bf4_inv_p(v[4*r], v[4*r+1], v[4*r+2], v[4*r+3], n1);
    }

    v[4]  = cmulc_p(v[4],  w);
    v[8]  = cmulc_p(v[8],  w2);
    v[12] = cmulc_p(v[12], w3);
    bf4_inv_p(v[0], v[4], v[8], v[12], n1);
    v[5]  = cmulc_p(v[5],  cmul(w,  W16_1));
    v[9]  = cmulc_p(v[9],  cmul(w2, W16_2));
    v[13] = cmulc_p(v[13], cmul(w3, W16_3));
    bf4_inv_p(v[1], v[5], v[9], v[13], n1);
    v[6]  = cmulc_p(v[6],  cmul(w,  W16_2));
    v[10] = cmulc_p(v[10], cmul(w2, W16_4));
    v[14] = cmulc_p(v[14], cmul(w3, W16_6));
    bf4_inv_p(v[2], v[6], v[10], v[14], n1);
    v[7]  = cmulc_p(v[7],  cmul(w,  W16_3));
    v[11] = cmulc_p(v[11], cmul(w2, W16_6));
    v[15] = cmulc_p(v[15], cmul(w3, W16_9));
    bf4_inv_p(v[3], v[7], v[11], v[15], n1);

    #pragma unroll
    for (int s = 0; s < 16; s++) dptr[skew(s * q2)] = v[s];
    __syncthreads();
}

// ---- pointwise pair core: a = Z[k], b = Z[-k] -> P[k], P[-k] with scale c
__device__ __forceinline__ void pw_pair(ull& a, ull& b, float c) {
    float2 A = upk(a), B = upk(b);
    float Ax = A.x * A.x - A.y * A.y, Ay = 2.0f * A.x * A.y;
    float Bx = B.x * B.x - B.y * B.y, By = 2.0f * B.x * B.y;
    float px = (Ay + By) * c;
    float py = (Bx - Ax) * c;
    a = pk(px,  py);
    b = pk(px, -py);
}

// ---- fused middle round: fwd m=4 stage + pointwise + inv m=4 stage.
// Quad b (points 4b+t = Z[rb + 4096 t], rb = dr4(4b)) pairs with quad
// bp = dr4(16384 - rb) >> 2 via t <-> 3-t.  b=0 special: (0,0),(1,3),(2,2).
__device__ __forceinline__ void middle_round(float2* data, int tid)
{
    ull n1 = NEGONE2;
    const float c = 0.25f / ((float)FFT_N * (float)FFT_N);
    ull* dp = (ull*)data;
    #pragma unroll 1
    for (int rep = 0; rep < FFT_N / 4 / NTHREADS; rep++) {
        int b  = tid + NTHREADS * rep;          // quad index
        int rb = dr4(4 * b);
        int bp = (b == 0) ? 0 : (dr4(16384 - rb) >> 2);
        if (bp < b) continue;                   // pair owned by smaller quad

        int ia = skew(4 * b);                   // quad contiguous: ia..ia+3
        ull a0 = dp[ia], a1 = dp[ia+1], a2 = dp[ia+2], a3 = dp[ia+3];
        bf4_fwd_p(a0, a1, a2, a3, n1);

        if (bp == b) {
            if (b == 0) {
                pw_pair(a0, a0, c);             // k=0 self
                pw_pair(a1, a3, c);             // 4096 <-> 12288
                pw_pair(a2, a2, c);             // Nyquist self
            } else {
                pw_pair(a0, a3, c);
                pw_pair(a1, a2, c);
            }
            bf4_inv_p(a0, a1, a2, a3, n1);
            dp[ia] = a0; dp[ia+1] = a1; dp[ia+2] = a2; dp[ia+3] = a3;
        } else {
            int ib = skew(4 * bp);
            ull b0 = dp[ib], b1 = dp[ib+1], b2 = dp[ib+2], b3 = dp[ib+3];
            bf4_fwd_p(b0, b1, b2, b3, n1);

            pw_pair(a0, b3, c);
            pw_pair(a1, b2, c);
            pw_pair(a2, b1, c);
            pw_pair(a3, b0, c);

            bf4_inv_p(a0, a1, a2, a3, n1);
            bf4_inv_p(b0, b1, b2, b3, n1);
            dp[ia] = a0; dp[ia+1] = a1; dp[ia+2] = a2; dp[ia+3] = a3;
            dp[ib] = b0; dp[ib+1] = b1; dp[ib+2] = b2; dp[ib+3] = b3;
        }
    }
    __syncthreads();
}

// ---- last inverse round (stages 2^12 then 2^14), fused global store.
__device__ __forceinline__ void inv_round_last(float2* data, const float2* tw,
                                               float* __restrict__ yr, int tid)
{
    ull n1 = NEGONE2;
    int u = tid;                                // base = u, q2 = 1024
    ull* dptr = (ull*)(data + skew(u));
    ull v[16];
    #pragma unroll
    for (int s = 0; s < 16; s++) v[s] = dptr[skew(s * 1024)];

    float2 w  = tw[skew(u)];
    float2 w2 = cmul(w, w);
    float2 w3 = cmul(w2, w);
    float2 p1 = cmul(w2, w2);
    float2 p2 = cmul(p1, p1);
    float2 p3 = cmul(p2, p1);

    // undo stage m/4 = 4096
    #pragma unroll
    for (int r = 0; r < 4; r++) {
        v[4*r+1] = cmulc_p(v[4*r+1], p1);
        v[4*r+2] = cmulc_p(v[4*r+2], p2);
        v[4*r+3] = cmulc_p(v[4*r+3], p3);
        bf4_inv_p(v[4*r], v[4*r+1], v[4*r+2], v[4*r+3], n1);
    }

    // undo stage m = 16384; only low-half real parts are kept.
    v[4]  = cmulc_p(v[4],  w);
    v[8]  = cmulc_p(v[8],  w2);
    v[12] = cmulc_p(v[12], w3);
    v[5]  = cmulc_p(v[5],  cmul(w,  W16_1));
    v[9]  = cmulc_p(v[9],  cmul(w2, W16_2));
    v[13] = cmulc_p(v[13], cmul(w3, W16_3));
    v[6]  = cmulc_p(v[6],  cmul(w,  W16_2));
    v[10] = cmulc_p(v[10], cmul(w2, W16_4));
    v[14] = cmulc_p(v[14], cmul(w3, W16_6));
    v[7]  = cmulc_p(v[7],  cmul(w,  W16_3));
    v[11] = cmulc_p(v[11], cmul(w2, W16_6));
    v[15] = cmulc_p(v[15], cmul(w3, W16_9));

    #pragma unroll
    for (int d = 0; d < 4; d++) {
        float2 c0 = upk(v[d]), c1 = upk(v[d+4]), c2 = upk(v[d+8]), c3 = upk(v[d+12]);
        float out0_re = (c0.x + c2.x) + (c1.x + c3.x);
        float out1_re = (c0.x - c2.x) - (c1.y - c3.y);
        yr[u + d * 1024]       = out0_re;
        yr[u + (d + 4) * 1024] = out1_re;
    }
}

__global__ void __launch_bounds__(NTHREADS, 1)
fftconv_kernel(const float* __restrict__ X,
               const float* __restrict__ H,
               float* __restrict__ Y)
{
    extern __shared__ float2 smem_f2[];
    float2* data = smem_f2;
    float2* tw   = smem_f2 + DATA_SKEW_SIZE;

    const int tid = threadIdx.x;
    const size_t row = blockIdx.x;

    // twiddle table: W_N^j, j < 1024
    if (tid < 1024) {
        float s, c;
        sincospif(-(float)tid * (1.0f / 8192.0f), &s, &c);
        tw[skew(tid)] = make_float2(c, s);
    }
    __syncthreads();

    const float* xr = X + row * SEQ_L;
    const float* hr = H + row * SEQ_L;

    // forward stages (14,12 | 10,8 | 6,4), fused pointwise (incl. stage 2),
    // inverse stages (4,6 | 8,10 | 12,14)
    fwd_round1(xr, hr, data, tw, tid);
    super_fwd<10>(data, tw, tid);
    super_fwd<6> (data, tw, tid);
    middle_round(data, tid);
    super_inv<6> (data, tw, tid);
    super_inv<10>(data, tw, tid);
    inv_round_last(data, tw, Y + row * SEQ_L, tid);
}

extern "C" void kernel_launch(void* const* d_in, const int* in_sizes, int n_in,
                              void* d_out, int out_size)
{
    const float* x = (const float*)d_in[0];
    const float* h = (const float*)d_in[1];
    float* y = (float*)d_out;

    int B = in_sizes[0] / SEQ_L;

    cudaFuncSetAttribute(fftconv_kernel,
                         cudaFuncAttributeMaxDynamicSharedMemorySize, SMEM_BYTES);
    fftconv_kernel<<<B, NTHREADS, SMEM_BYTES>>>(x, h, y);
}